// round 3
// baseline (speedup 1.0000x reference)
#include <cuda_runtime.h>
#include <cuda_bf16.h>

// Distance_74406013436418: trilinear SDF interpolation + finite-difference
// normals + hinge loss.
//
// Inputs (metadata order):
//   d_in[0] pss        [B,3,N]   float32
//   d_in[1] sdf_grids  [B,D,D,D] float32
//   d_in[2] first      [B,3]     float32
//   d_in[3] coef       [B,3]     float32
//   d_in[4] max_limit  [B,3]     float32
// Output (float32, concatenated in reference return order):
//   [0,            B*N)      dss   [B,N]
//   [B*N,          4*B*N)    nss   [B,N,3]
//   [4*B*N,        4*B*N+1)  loss  scalar

#define EPS 1e-5f

__global__ __launch_bounds__(256)
void sdf_trilinear_kernel(const float* __restrict__ pss,
                          const float* __restrict__ grid,
                          const float* __restrict__ first,
                          const float* __restrict__ coef,
                          const float* __restrict__ maxl,
                          float* __restrict__ dss,
                          float* __restrict__ nss,
                          float* __restrict__ loss,
                          int N, int D, int total)
{
    int t = blockIdx.x * blockDim.x + threadIdx.x;

    float my_loss = 0.0f;

    if (t < total) {
        int b = t / N;
        int n = t - b * N;

        // point coords (coalesced across threads: stride-1 in n)
        float px = pss[((size_t)b * 3 + 0) * N + n];
        float py = pss[((size_t)b * 3 + 1) * N + n];
        float pz = pss[((size_t)b * 3 + 2) * N + n];

        float f0x = first[b * 3 + 0], f0y = first[b * 3 + 1], f0z = first[b * 3 + 2];
        float cx  = coef[b * 3 + 0],  cy  = coef[b * 3 + 1],  cz  = coef[b * 3 + 2];
        float mx  = maxl[b * 3 + 0],  my  = maxl[b * 3 + 1],  mz  = maxl[b * 3 + 2];

        float fx_full = fmaxf(fminf((px - f0x) * cx, mx), 0.0f);
        float fy_full = fmaxf(fminf((py - f0y) * cy, my), 0.0f);
        float fz_full = fmaxf(fminf((pz - f0z) * cz, mz), 0.0f);

        float bx = floorf(fx_full);
        float by = floorf(fy_full);
        float bz = floorf(fz_full);
        float fx = fx_full - bx;
        float fy = fy_full - by;
        float fz = fz_full - bz;

        int ix = (int)bx, iy = (int)by, iz = (int)bz;

        const float* g = grid + (size_t)b * D * D * D
                              + (size_t)ix * D * D
                              + (size_t)iy * D
                              + (size_t)iz;
        const int DD = D * D;

        // 8 gathers issued back-to-back (max MLP, all independent)
        float c000 = __ldg(g);
        float c001 = __ldg(g + 1);
        float c010 = __ldg(g + D);
        float c011 = __ldg(g + D + 1);
        float c100 = __ldg(g + DD);
        float c101 = __ldg(g + DD + 1);
        float c110 = __ldg(g + DD + D);
        float c111 = __ldg(g + DD + D + 1);

        float wx0 = 1.0f - fx, wx1 = fx;
        float wy0 = 1.0f - fy, wy1 = fy;
        float wz0 = 1.0f - fz, wz1 = fz;

        // trilinear value (lerp chain: z, then y, then x)
        float a00 = fmaf(fz, c001 - c000, c000);
        float a01 = fmaf(fz, c011 - c010, c010);
        float a10 = fmaf(fz, c101 - c100, c100);
        float a11 = fmaf(fz, c111 - c110, c110);
        float b0  = fmaf(fy, a01 - a00, a00);
        float b1  = fmaf(fy, a11 - a10, a10);
        float d   = fmaf(fx, b1 - b0, b0);

        // finite-difference normals
        // n_z: diff along z (3rd index), weighted by wx, wy
        float dz00 = c001 - c000, dz01 = c011 - c010;
        float dz10 = c101 - c100, dz11 = c111 - c110;
        float nz = (dz00 * wy0 + dz01 * wy1) * wx0
                 + (dz10 * wy0 + dz11 * wy1) * wx1;

        // n_y: diff along y (2nd index), weighted by wx, wz
        float dy00 = c010 - c000, dy01 = c011 - c001;
        float dy10 = c110 - c100, dy11 = c111 - c101;
        float ny = (dy00 * wz0 + dy01 * wz1) * wx0
                 + (dy10 * wz0 + dy11 * wz1) * wx1;

        // n_x: diff along x (1st index), weighted by wy, wz
        float dx00 = c100 - c000, dx01 = c101 - c001;
        float dx10 = c110 - c010, dx11 = c111 - c011;
        float nx = (dx00 * wz0 + dx01 * wz1) * wy0
                 + (dx10 * wz0 + dx11 * wz1) * wy1;

        float norm = sqrtf(nx * nx + ny * ny + nz * nz);
        float inv  = 1.0f / fmaxf(norm, EPS);

        dss[t] = d;
        nss[3 * (size_t)t + 0] = nx * inv;
        nss[3 * (size_t)t + 1] = ny * inv;
        nss[3 * (size_t)t + 2] = nz * inv;

        my_loss = -fminf(d, 0.0f);
    }

    // block reduction of loss, one atomic per block
    __shared__ float warp_sums[8];
    int lane = threadIdx.x & 31;
    int warp = threadIdx.x >> 5;

    #pragma unroll
    for (int off = 16; off > 0; off >>= 1)
        my_loss += __shfl_down_sync(0xFFFFFFFFu, my_loss, off);
    if (lane == 0) warp_sums[warp] = my_loss;
    __syncthreads();

    if (warp == 0) {
        float s = (lane < (blockDim.x >> 5)) ? warp_sums[lane] : 0.0f;
        #pragma unroll
        for (int off = 4; off > 0; off >>= 1)
            s += __shfl_down_sync(0xFFFFFFFFu, s, off);
        if (lane == 0)
            atomicAdd(loss, s);
    }
}

extern "C" void kernel_launch(void* const* d_in, const int* in_sizes, int n_in,
                              void* d_out, int out_size)
{
    const float* pss   = (const float*)d_in[0];
    const float* grid  = (const float*)d_in[1];
    const float* first = (const float*)d_in[2];
    const float* coef  = (const float*)d_in[3];
    const float* maxl  = (const float*)d_in[4];

    // B from first [B,3]; N from pss [B,3,N]; D from grid [B,D,D,D]
    int B = in_sizes[2] / 3;
    int N = in_sizes[0] / (3 * B);
    // D = cbrt(in_sizes[1]/B); grids are 192^3 here but derive robustly
    long per_b = (long)in_sizes[1] / B;
    int D = 1;
    while ((long)(D + 1) * (D + 1) * (D + 1) <= per_b) D++;

    int total = B * N;

    float* dss  = (float*)d_out;
    float* nss  = dss + (size_t)total;
    float* loss = dss + (size_t)4 * total;

    // zero the loss accumulator (d_out is poisoned) — capturable async memset
    cudaMemsetAsync(loss, 0, sizeof(float));

    int threads = 256;
    int blocks  = (total + threads - 1) / threads;
    sdf_trilinear_kernel<<<blocks, threads>>>(pss, grid, first, coef, maxl,
                                              dss, nss, loss, N, D, total);
}